// round 1
// baseline (speedup 1.0000x reference)
#include <cuda_runtime.h>

#define BATCH 32
#define NPTS 512
#define DIM 1024
#define KCL 64
#define NROWS (BATCH*NPTS)      /* 16384 */
#define OUTF 1024
#define IN2 (2*DIM*KCL)         /* 131072 */

// ---------------- scratch (device globals: no allocations allowed) ----------
__device__ float g_act[NROWS*KCL];          // 4 MB: raw act, then softmaxed act
__device__ float g_colsum[KCL];
__device__ float g_colsumsq[KCL];
__device__ float g_asum[BATCH*KCL];
__device__ float g_fv1[BATCH*DIM*KCL];      // 8 MB
__device__ float g_fv2[BATCH*DIM*KCL];      // 8 MB
__device__ float g_colnorm[BATCH*KCL];
__device__ float g_norm1[BATCH];
__device__ float g_norm2[BATCH];
__device__ float g_fvcat[BATCH*IN2];        // 16 MB
__device__ float g_fvout[BATCH*OUTF];
__device__ float g_gates[BATCH*OUTF];

typedef unsigned long long ull;

// ---------------- f32x2 helpers (FFMA2: 2 FMAs / instr on sm_103a) ----------
__device__ __forceinline__ ull pack2(float lo, float hi){
  ull r;
  asm("mov.b64 %0, {%1, %2};" : "=l"(r)
      : "r"(__float_as_uint(lo)), "r"(__float_as_uint(hi)));
  return r;
}
__device__ __forceinline__ void ffma2(ull &d, ull a, ull b){
  asm("fma.rn.f32x2 %0, %1, %2, %3;" : "=l"(d) : "l"(a), "l"(b), "l"(d));
}
__device__ __forceinline__ ull mul2(ull a, ull b){
  ull r; asm("mul.rn.f32x2 %0, %1, %2;" : "=l"(r) : "l"(a), "l"(b)); return r;
}
__device__ __forceinline__ float lo32(ull v){ return __uint_as_float((unsigned)(v & 0xffffffffull)); }
__device__ __forceinline__ float hi32(ull v){ return __uint_as_float((unsigned)(v >> 32)); }

// ---------------- K0: zero the atomic accumulators ---------------------------
__global__ void zero_kernel(){
  int i = blockIdx.x*blockDim.x + threadIdx.x;
  if (i < BATCH*OUTF){ g_fvout[i] = 0.f; g_gates[i] = 0.f; }
  if (i < BATCH*KCL)  g_colnorm[i] = 0.f;
  if (i < KCL){ g_colsum[i] = 0.f; g_colsumsq[i] = 0.f; }
  if (i < BATCH){ g_norm1[i] = 0.f; g_norm2[i] = 0.f; }
}

// ---------------- K1: act_raw = X @ Wc  (+ column sum / sumsq for BN1) ------
// grid 256, block 256. BM=64 rows, BN=64(all K), BK=32.
__global__ __launch_bounds__(256) void gemm_act_kernel(
    const float* __restrict__ x, const float* __restrict__ wc){
  __shared__ float As[64][33];
  __shared__ float Bs[32][64];
  __shared__ float sSum[KCL], sSq[KCL];
  int tid = threadIdx.x;
  int row0 = blockIdx.x * 64;
  int tx = tid & 15, ty = tid >> 4;
  ull acc[4][2];
  #pragma unroll
  for (int i=0;i<4;i++){ acc[i][0]=0ull; acc[i][1]=0ull; }
  if (tid < KCL){ sSum[tid]=0.f; sSq[tid]=0.f; }

  for (int d0=0; d0<DIM; d0+=32){
    #pragma unroll
    for (int l=tid; l<2048; l+=256){
      int r=l>>5, c=l&31;
      As[r][c] = x[(row0+r)*DIM + d0 + c];
    }
    #pragma unroll
    for (int l=tid; l<2048; l+=256){
      int r=l>>6, c=l&63;
      Bs[r][c] = wc[(d0+r)*KCL + c];
    }
    __syncthreads();
    #pragma unroll
    for (int dd=0; dd<32; dd++){
      const ull* bp = reinterpret_cast<const ull*>(&Bs[dd][tx*4]);
      ull b0 = bp[0], b1 = bp[1];
      #pragma unroll
      for (int i=0;i<4;i++){
        float a = As[ty*4+i][dd];
        ull ap = pack2(a, a);
        ffma2(acc[i][0], ap, b0);
        ffma2(acc[i][1], ap, b1);
      }
    }
    __syncthreads();
  }
  float ps[4]={0,0,0,0}, pq[4]={0,0,0,0};
  #pragma unroll
  for (int i=0;i<4;i++){
    float v0=lo32(acc[i][0]), v1=hi32(acc[i][0]);
    float v2=lo32(acc[i][1]), v3=hi32(acc[i][1]);
    *reinterpret_cast<float4*>(&g_act[(row0+ty*4+i)*KCL + tx*4]) =
        make_float4(v0,v1,v2,v3);
    ps[0]+=v0; ps[1]+=v1; ps[2]+=v2; ps[3]+=v3;
    pq[0]+=v0*v0; pq[1]+=v1*v1; pq[2]+=v2*v2; pq[3]+=v3*v3;
  }
  #pragma unroll
  for (int j=0;j<4;j++){
    atomicAdd(&sSum[tx*4+j], ps[j]);
    atomicAdd(&sSq [tx*4+j], pq[j]);
  }
  __syncthreads();
  if (tid < KCL){
    atomicAdd(&g_colsum[tid],   sSum[tid]);
    atomicAdd(&g_colsumsq[tid], sSq[tid]);
  }
}

// ---------------- K2: BN1 (train-mode batch stats) + softmax per row --------
// grid NROWS, block 64 (one thread per k)
__global__ __launch_bounds__(64) void bn_softmax_kernel(
    const float* __restrict__ gamma, const float* __restrict__ beta){
  int row = blockIdx.x;
  int k = threadIdx.x;
  int lane = k & 31, wrp = k >> 5;
  const float inv_n = 1.f / (float)NROWS;
  float mean = g_colsum[k] * inv_n;
  float var  = g_colsumsq[k] * inv_n - mean*mean;
  float v = g_act[row*KCL + k];
  float vn = (v - mean) * rsqrtf(var + 1e-5f) * gamma[k] + beta[k];

  __shared__ float smax[2], ssum[2];
  float m = vn;
  #pragma unroll
  for (int o=16;o>0;o>>=1) m = fmaxf(m, __shfl_xor_sync(0xffffffffu, m, o));
  if (lane==0) smax[wrp] = m;
  __syncthreads();
  m = fmaxf(smax[0], smax[1]);
  float e = expf(vn - m);
  float s = e;
  #pragma unroll
  for (int o=16;o>0;o>>=1) s += __shfl_xor_sync(0xffffffffu, s, o);
  if (lane==0) ssum[wrp] = s;
  __syncthreads();
  s = ssum[0] + ssum[1];
  g_act[row*KCL + k] = e / s;
}

// ---------------- K3: a_sum[b,k] = sum_n act[b,n,k] -------------------------
__global__ __launch_bounds__(64) void asum_kernel(){
  int b = blockIdx.x, k = threadIdx.x;
  float s = 0.f;
  for (int n=0; n<NPTS; n++) s += g_act[(b*NPTS + n)*KCL + k];
  g_asum[b*KCL + k] = s;
}

// ---------------- K4: fv1[b,d,k]=sum_n a*x ; fv2=sum_n a*x*x ----------------
// grid (32 dtiles, 32 b), block 256. BD=32, NC=16.
__global__ __launch_bounds__(256) void einsum_kernel(const float* __restrict__ x){
  __shared__ float xs[16][32];
  __shared__ float as_[16][64];
  int tid = threadIdx.x;
  int b = blockIdx.y, dt0 = blockIdx.x*32;
  int kg = tid & 15, dg = tid >> 4;
  int k0 = kg*4, d0 = dg*2;
  ull a1[4], a2[4];
  #pragma unroll
  for (int j=0;j<4;j++){ a1[j]=0ull; a2[j]=0ull; }

  for (int n0=0; n0<NPTS; n0+=16){
    #pragma unroll
    for (int l=tid; l<512; l+=256){
      int r=l>>5, c=l&31;
      xs[r][c] = x[(b*NPTS + n0 + r)*DIM + dt0 + c];
    }
    #pragma unroll
    for (int l=tid; l<1024; l+=256){
      int r=l>>6, c=l&63;
      as_[r][c] = g_act[(b*NPTS + n0 + r)*KCL + c];
    }
    __syncthreads();
    #pragma unroll
    for (int nn=0; nn<16; nn++){
      ull xp  = *reinterpret_cast<const ull*>(&xs[nn][d0]);
      ull xxp = mul2(xp, xp);
      float4 av = *reinterpret_cast<const float4*>(&as_[nn][k0]);
      ull ap0 = pack2(av.x, av.x), ap1 = pack2(av.y, av.y);
      ull ap2 = pack2(av.z, av.z), ap3 = pack2(av.w, av.w);
      ffma2(a1[0], xp,  ap0); ffma2(a1[1], xp,  ap1);
      ffma2(a1[2], xp,  ap2); ffma2(a1[3], xp,  ap3);
      ffma2(a2[0], xxp, ap0); ffma2(a2[1], xxp, ap1);
      ffma2(a2[2], xxp, ap2); ffma2(a2[3], xxp, ap3);
    }
    __syncthreads();
  }
  int dglob = dt0 + d0;
  float4 lo1 = make_float4(lo32(a1[0]),lo32(a1[1]),lo32(a1[2]),lo32(a1[3]));
  float4 hi1 = make_float4(hi32(a1[0]),hi32(a1[1]),hi32(a1[2]),hi32(a1[3]));
  float4 lo2 = make_float4(lo32(a2[0]),lo32(a2[1]),lo32(a2[2]),lo32(a2[3]));
  float4 hi2 = make_float4(hi32(a2[0]),hi32(a2[1]),hi32(a2[2]),hi32(a2[3]));
  *reinterpret_cast<float4*>(&g_fv1[(b*DIM + dglob  )*KCL + k0]) = lo1;
  *reinterpret_cast<float4*>(&g_fv1[(b*DIM + dglob+1)*KCL + k0]) = hi1;
  *reinterpret_cast<float4*>(&g_fv2[(b*DIM + dglob  )*KCL + k0]) = lo2;
  *reinterpret_cast<float4*>(&g_fv2[(b*DIM + dglob+1)*KCL + k0]) = hi2;
}

// ---------------- K5a: FV transforms + per-(b,k) and per-b sumsq ------------
// grid (8 d-chunks of 128, 32 b), block 256. thread: k=tid&63, dg=tid>>6.
__global__ __launch_bounds__(256) void fv_transform_kernel(
    const float* __restrict__ covw, const float* __restrict__ cw2w){
  int b = blockIdx.y, chunk = blockIdx.x;
  int tid = threadIdx.x;
  int k = tid & 63, dg = tid >> 6;
  float asum_k = g_asum[b*KCL + k];
  float pcol = 0.f, pn2 = 0.f;
  #pragma unroll 4
  for (int i=0;i<32;i++){
    int d = chunk*128 + i*4 + dg;
    int widx = d*KCL + k;
    int idx  = (b*DIM + d)*KCL + k;
    float cw2 = cw2w[widx];
    float cov = covw[widx];
    float cwv = cov*cov + 1e-6f;
    float f1r = g_fv1[idx], f2r = g_fv2[idx];
    float f1t = (f1r - asum_k*cw2) / cwv;
    float f2t = (asum_k*cw2*cw2 + f2r - 2.f*f1r*cw2) / (cwv*cwv) - asum_k;
    g_fv1[idx] = f1t; g_fv2[idx] = f2t;
    pcol += f1t*f1t; pn2 += f2t*f2t;
  }
  __shared__ float sCol[KCL];
  __shared__ float sw[8];
  if (tid < KCL) sCol[tid] = 0.f;
  __syncthreads();
  atomicAdd(&sCol[k], pcol);
  #pragma unroll
  for (int o=16;o>0;o>>=1) pn2 += __shfl_xor_sync(0xffffffffu, pn2, o);
  if ((tid&31)==0) sw[tid>>5] = pn2;
  __syncthreads();
  if (tid < KCL) atomicAdd(&g_colnorm[b*KCL + tid], sCol[tid]);
  if (tid == 0){
    float t=0.f;
    #pragma unroll
    for (int i=0;i<8;i++) t += sw[i];
    atomicAdd(&g_norm2[b], t);
  }
}

// ---------------- K5b: fv1 column-normalize, fv2 full-normalize, stage fvcat
__global__ __launch_bounds__(256) void fv_norm_kernel(){
  int b = blockIdx.y, chunk = blockIdx.x;
  int tid = threadIdx.x;
  int k = tid & 63, dg = tid >> 6;
  float inv1 = 1.f / fmaxf(sqrtf(g_colnorm[b*KCL + k]), 1e-12f);
  float inv2 = 1.f / fmaxf(sqrtf(g_norm2[b]), 1e-12f);
  float p1 = 0.f;
  #pragma unroll 4
  for (int i=0;i<32;i++){
    int d = chunk*128 + i*4 + dg;
    int idx = (b*DIM + d)*KCL + k;
    float f1 = g_fv1[idx] * inv1;
    g_fvcat[b*IN2 + d*KCL + k] = f1;
    p1 += f1*f1;
    g_fvcat[b*IN2 + DIM*KCL + d*KCL + k] = g_fv2[idx] * inv2;
  }
  #pragma unroll
  for (int o=16;o>0;o>>=1) p1 += __shfl_xor_sync(0xffffffffu, p1, o);
  __shared__ float sw[8];
  if ((tid&31)==0) sw[tid>>5] = p1;
  __syncthreads();
  if (tid == 0){
    float t=0.f;
    #pragma unroll
    for (int i=0;i<8;i++) t += sw[i];
    atomicAdd(&g_norm1[b], t);
  }
}

// ---------------- K5c: final full-vector normalize of fv1 half --------------
__global__ __launch_bounds__(256) void fv1_final_kernel(){
  int idx = blockIdx.x*256 + threadIdx.x;     // over BATCH*DIM*KCL = 2M
  int b = idx >> 16;
  int off = idx & 65535;
  float inv = 1.f / fmaxf(sqrtf(g_norm1[b]), 1e-12f);
  g_fvcat[b*IN2 + off] *= inv;
}

// ---------------- K6/K7a: out[32,1024] += A[32,lda-chunk] @ W[.,1024] -------
// which=0: A=g_fvcat -> g_fvout (hidden1). which=1: A=g_fvout -> g_gates.
// grid (8 o-tiles of 128, nsplit), block 256; split-K via float atomics.
__global__ __launch_bounds__(256) void gemm_fc_kernel(
    const float* __restrict__ W, int lda, int ichunk, int which){
  const float* A = which ? g_fvout : g_fvcat;
  float* out     = which ? g_gates : g_fvout;
  __shared__ float Ws[8][128];
  __shared__ float fs[8][32];
  int tid = threadIdx.x;
  int o0 = blockIdx.x * 128;
  int i0 = blockIdx.y * ichunk;
  int og = tid & 15, bg = tid >> 4;
  int o_local = og*8, b_local = bg*2;
  ull acc[2][4];
  #pragma unroll
  for (int bb=0;bb<2;bb++)
    #pragma unroll
    for (int j=0;j<4;j++) acc[bb][j] = 0ull;

  for (int ic=0; ic<ichunk; ic+=8){
    int i = i0 + ic;
    #pragma unroll
    for (int l=tid; l<1024; l+=256){
      int r=l>>7, c=l&127;
      Ws[r][c] = W[(i+r)*OUTF + o0 + c];
    }
    { int r=tid>>5, c=tid&31; fs[r][c] = A[c*lda + i + r]; }
    __syncthreads();
    #pragma unroll
    for (int ii=0; ii<8; ii++){
      const ull* wp = reinterpret_cast<const ull*>(&Ws[ii][o_local]);
      ull w0=wp[0], w1=wp[1], w2=wp[2], w3=wp[3];
      float f0 = fs[ii][b_local], f1 = fs[ii][b_local+1];
      ull p0 = pack2(f0,f0), p1 = pack2(f1,f1);
      ffma2(acc[0][0], p0, w0); ffma2(acc[0][1], p0, w1);
      ffma2(acc[0][2], p0, w2); ffma2(acc[0][3], p0, w3);
      ffma2(acc[1][0], p1, w0); ffma2(acc[1][1], p1, w1);
      ffma2(acc[1][2], p1, w2); ffma2(acc[1][3], p1, w3);
    }
    __syncthreads();
  }
  #pragma unroll
  for (int bb=0;bb<2;bb++)
    #pragma unroll
    for (int j=0;j<4;j++){
      int base = (b_local+bb)*OUTF + o0 + o_local + j*2;
      atomicAdd(&out[base],   lo32(acc[bb][j]));
      atomicAdd(&out[base+1], hi32(acc[bb][j]));
    }
}

// ---------------- K7b: BN2 (batch stats over 32) + sigmoid gate -------------
__global__ __launch_bounds__(256) void bn2_gate_kernel(
    const float* __restrict__ g2, const float* __restrict__ b2,
    float* __restrict__ out){
  int o = blockIdx.x*blockDim.x + threadIdx.x;   // 0..1023
  float m=0.f, s=0.f;
  #pragma unroll 8
  for (int b=0;b<BATCH;b++){ float v = g_gates[b*OUTF + o]; m += v; s += v*v; }
  m *= (1.f/BATCH);
  float var = s*(1.f/BATCH) - m*m;
  float rs = rsqrtf(var + 1e-5f);
  float ga = g2[o], be = b2[o];
  #pragma unroll 8
  for (int b=0;b<BATCH;b++){
    float v = (g_gates[b*OUTF + o] - m)*rs*ga + be;
    float sig = 1.f/(1.f + expf(-v));
    out[b*OUTF + o] = g_fvout[b*OUTF + o] * sig;
  }
}

// ---------------------------------------------------------------------------
extern "C" void kernel_launch(void* const* d_in, const int* in_sizes, int n_in,
                              void* d_out, int out_size){
  const float* x   = (const float*)d_in[0];   // [32,512,1024]
  const float* wc  = (const float*)d_in[1];   // [1024,64]
  const float* cov = (const float*)d_in[2];   // [1024,64]
  const float* cw2 = (const float*)d_in[3];   // [1,1024,64]
  const float* w1  = (const float*)d_in[4];   // [131072,1024]
  const float* g1  = (const float*)d_in[5];   // [64]
  const float* b1  = (const float*)d_in[6];   // [64]
  const float* wg  = (const float*)d_in[7];   // [1024,1024]
  const float* g2  = (const float*)d_in[8];   // [1024]
  const float* b2  = (const float*)d_in[9];   // [1024]
  float* out = (float*)d_out;                 // [32,1024]

  zero_kernel<<<128, 256>>>();
  gemm_act_kernel<<<256, 256>>>(x, wc);
  bn_softmax_kernel<<<NROWS, 64>>>(g1, b1);
  asum_kernel<<<BATCH, KCL>>>();
  einsum_kernel<<<dim3(32, 32), 256>>>(x);
  fv_transform_kernel<<<dim3(8, 32), 256>>>(cov, cw2);
  fv_norm_kernel<<<dim3(8, 32), 256>>>();
  fv1_final_kernel<<<8192, 256>>>();
  gemm_fc_kernel<<<dim3(8, 128), 256>>>(w1, IN2, 1024, 0);  // hidden1
  gemm_fc_kernel<<<dim3(8, 8),   256>>>(wg, OUTF, 128, 1);  // gating
  bn2_gate_kernel<<<4, 256>>>(g2, b2, out);
}

// round 2
// speedup vs baseline: 1.4949x; 1.4949x over previous
#include <cuda_runtime.h>

#define BATCH 32
#define NPTS 512
#define DIM 1024
#define KCL 64
#define NROWS (BATCH*NPTS)      /* 16384 */
#define OUTF 1024
#define IN2 (2*DIM*KCL)         /* 131072 */

// ---------------- scratch (device globals: no allocations allowed) ----------
__device__ float g_act[NROWS*KCL];          // 4 MB
__device__ float g_colsum[KCL];
__device__ float g_colsumsq[KCL];
__device__ float g_asum[BATCH*KCL];
__device__ float g_fv1[BATCH*DIM*KCL];      // 8 MB
__device__ float g_fv2[BATCH*DIM*KCL];      // 8 MB
__device__ float g_colnorm[BATCH*KCL];
__device__ float g_norm1[BATCH];
__device__ float g_norm2[BATCH];
__device__ float g_fvcat[BATCH*IN2];        // 16 MB
__device__ float g_fvout[BATCH*OUTF];
__device__ float g_gates[BATCH*OUTF];

typedef unsigned long long ull;

// ---------------- f32x2 helpers (FFMA2: 2 FMAs / instr on sm_103a) ----------
__device__ __forceinline__ ull pack2(float lo, float hi){
  ull r;
  asm("mov.b64 %0, {%1, %2};" : "=l"(r)
      : "r"(__float_as_uint(lo)), "r"(__float_as_uint(hi)));
  return r;
}
__device__ __forceinline__ void ffma2(ull &d, ull a, ull b){
  asm("fma.rn.f32x2 %0, %1, %2, %3;" : "=l"(d) : "l"(a), "l"(b), "l"(d));
}
__device__ __forceinline__ ull mul2(ull a, ull b){
  ull r; asm("mul.rn.f32x2 %0, %1, %2;" : "=l"(r) : "l"(a), "l"(b)); return r;
}
__device__ __forceinline__ float lo32(ull v){ return __uint_as_float((unsigned)(v & 0xffffffffull)); }
__device__ __forceinline__ float hi32(ull v){ return __uint_as_float((unsigned)(v >> 32)); }

// ---------------- K0: zero the atomic accumulators ---------------------------
__global__ void zero_kernel(){
  int i = blockIdx.x*blockDim.x + threadIdx.x;
  if (i < BATCH*OUTF){ g_fvout[i] = 0.f; g_gates[i] = 0.f; }
  if (i < BATCH*KCL){ g_colnorm[i] = 0.f; g_asum[i] = 0.f; }
  if (i < KCL){ g_colsum[i] = 0.f; g_colsumsq[i] = 0.f; }
  if (i < BATCH){ g_norm1[i] = 0.f; g_norm2[i] = 0.f; }
}

// ---------------- K1: act_raw = X @ Wc  (+ column sum / sumsq for BN1) ------
// grid 256, block 256. BM=64 rows, BN=64(all K), BK=32.
__global__ __launch_bounds__(256) void gemm_act_kernel(
    const float* __restrict__ x, const float* __restrict__ wc){
  __shared__ float As[64][33];
  __shared__ float Bs[32][64];
  __shared__ float sSum[KCL], sSq[KCL];
  int tid = threadIdx.x;
  int row0 = blockIdx.x * 64;
  int tx = tid & 15, ty = tid >> 4;
  ull acc[4][2];
  #pragma unroll
  for (int i=0;i<4;i++){ acc[i][0]=0ull; acc[i][1]=0ull; }
  if (tid < KCL){ sSum[tid]=0.f; sSq[tid]=0.f; }

  for (int d0=0; d0<DIM; d0+=32){
    #pragma unroll
    for (int l=tid; l<2048; l+=256){
      int r=l>>5, c=l&31;
      As[r][c] = x[(row0+r)*DIM + d0 + c];
    }
    #pragma unroll
    for (int l=tid; l<2048; l+=256){
      int r=l>>6, c=l&63;
      Bs[r][c] = wc[(d0+r)*KCL + c];
    }
    __syncthreads();
    #pragma unroll
    for (int dd=0; dd<32; dd++){
      const ull* bp = reinterpret_cast<const ull*>(&Bs[dd][tx*4]);
      ull b0 = bp[0], b1 = bp[1];
      #pragma unroll
      for (int i=0;i<4;i++){
        float a = As[ty*4+i][dd];
        ull ap = pack2(a, a);
        ffma2(acc[i][0], ap, b0);
        ffma2(acc[i][1], ap, b1);
      }
    }
    __syncthreads();
  }
  float ps[4]={0,0,0,0}, pq[4]={0,0,0,0};
  #pragma unroll
  for (int i=0;i<4;i++){
    float v0=lo32(acc[i][0]), v1=hi32(acc[i][0]);
    float v2=lo32(acc[i][1]), v3=hi32(acc[i][1]);
    *reinterpret_cast<float4*>(&g_act[(row0+ty*4+i)*KCL + tx*4]) =
        make_float4(v0,v1,v2,v3);
    ps[0]+=v0; ps[1]+=v1; ps[2]+=v2; ps[3]+=v3;
    pq[0]+=v0*v0; pq[1]+=v1*v1; pq[2]+=v2*v2; pq[3]+=v3*v3;
  }
  #pragma unroll
  for (int j=0;j<4;j++){
    atomicAdd(&sSum[tx*4+j], ps[j]);
    atomicAdd(&sSq [tx*4+j], pq[j]);
  }
  __syncthreads();
  if (tid < KCL){
    atomicAdd(&g_colsum[tid],   sSum[tid]);
    atomicAdd(&g_colsumsq[tid], sSq[tid]);
  }
}

// ---------------- K2: BN1 + softmax (warp per row) + fused a_sum ------------
// grid 2048, block 256 = 8 warps = 8 rows (all same batch b).
__global__ __launch_bounds__(256) void bn_softmax_kernel(
    const float* __restrict__ gamma, const float* __restrict__ beta){
  __shared__ float sbuf[8][KCL];
  int tid = threadIdx.x;
  int w = tid >> 5, lane = tid & 31;
  int row = blockIdx.x*8 + w;
  int b = row >> 9;
  const float inv_n = 1.f / (float)NROWS;
  int k2 = 2*lane;
  float2 cs = *reinterpret_cast<const float2*>(&g_colsum[k2]);
  float2 cq = *reinterpret_cast<const float2*>(&g_colsumsq[k2]);
  float2 ga = *reinterpret_cast<const float2*>(&gamma[k2]);
  float2 be = *reinterpret_cast<const float2*>(&beta[k2]);
  float m0 = cs.x*inv_n, m1 = cs.y*inv_n;
  float sc0 = ga.x*rsqrtf(cq.x*inv_n - m0*m0 + 1e-5f);
  float sc1 = ga.y*rsqrtf(cq.y*inv_n - m1*m1 + 1e-5f);
  float sh0 = be.x - m0*sc0, sh1 = be.y - m1*sc1;

  float2 v = *reinterpret_cast<const float2*>(&g_act[row*KCL + k2]);
  float vn0 = v.x*sc0 + sh0, vn1 = v.y*sc1 + sh1;
  float mx = fmaxf(vn0, vn1);
  #pragma unroll
  for (int o=16;o>0;o>>=1) mx = fmaxf(mx, __shfl_xor_sync(0xffffffffu, mx, o));
  float e0 = __expf(vn0 - mx), e1 = __expf(vn1 - mx);
  float s = e0 + e1;
  #pragma unroll
  for (int o=16;o>0;o>>=1) s += __shfl_xor_sync(0xffffffffu, s, o);
  float inv = 1.f / s;
  float p0 = e0*inv, p1 = e1*inv;
  *reinterpret_cast<float2*>(&g_act[row*KCL + k2]) = make_float2(p0, p1);
  *reinterpret_cast<float2*>(&sbuf[w][k2]) = make_float2(p0, p1);
  __syncthreads();
  if (tid < KCL){
    float t = 0.f;
    #pragma unroll
    for (int i=0;i<8;i++) t += sbuf[i][tid];
    atomicAdd(&g_asum[b*KCL + tid], t);
  }
}

// ---------------- K4: fv1[b,d,k]=sum_n a*x ; fv2=sum_n a*x*x ----------------
// grid (16 dtiles, 32 b), block 256. tile 64d x 64k, thread 4d x 4k.
__global__ __launch_bounds__(256) void einsum_kernel(const float* __restrict__ x){
  __shared__ float xs[16][64];
  __shared__ float as_[16][64];
  int tid = threadIdx.x;
  int b = blockIdx.y, dt0 = blockIdx.x*64;
  int kg = tid & 15, dg = tid >> 4;
  int k0 = kg*4, d0 = dg*4;
  ull f1[4][2], f2[4][2];
  #pragma unroll
  for (int j=0;j<4;j++){ f1[j][0]=0ull; f1[j][1]=0ull; f2[j][0]=0ull; f2[j][1]=0ull; }

  for (int n0=0; n0<NPTS; n0+=16){
    {
      int r = tid>>4, c = (tid&15)*4;
      *reinterpret_cast<float4*>(&xs[r][c]) =
          *reinterpret_cast<const float4*>(&x[(b*NPTS + n0 + r)*DIM + dt0 + c]);
      *reinterpret_cast<float4*>(&as_[r][c]) =
          *reinterpret_cast<const float4*>(&g_act[(b*NPTS + n0 + r)*KCL + c]);
    }
    __syncthreads();
    #pragma unroll
    for (int nn=0; nn<16; nn++){
      const ull* xp = reinterpret_cast<const ull*>(&xs[nn][d0]);
      ull x01 = xp[0], x23 = xp[1];
      ull q01 = mul2(x01, x01), q23 = mul2(x23, x23);
      float4 av = *reinterpret_cast<const float4*>(&as_[nn][k0]);
      ull a0 = pack2(av.x, av.x), a1 = pack2(av.y, av.y);
      ull a2 = pack2(av.z, av.z), a3 = pack2(av.w, av.w);
      ffma2(f1[0][0], x01, a0); ffma2(f1[0][1], x23, a0);
      ffma2(f1[1][0], x01, a1); ffma2(f1[1][1], x23, a1);
      ffma2(f1[2][0], x01, a2); ffma2(f1[2][1], x23, a2);
      ffma2(f1[3][0], x01, a3); ffma2(f1[3][1], x23, a3);
      ffma2(f2[0][0], q01, a0); ffma2(f2[0][1], q23, a0);
      ffma2(f2[1][0], q01, a1); ffma2(f2[1][1], q23, a1);
      ffma2(f2[2][0], q01, a2); ffma2(f2[2][1], q23, a2);
      ffma2(f2[3][0], q01, a3); ffma2(f2[3][1], q23, a3);
    }
    __syncthreads();
  }
  #pragma unroll
  for (int du=0; du<4; du++){
    int half = du >> 1, sel = du & 1;
    float4 v1, v2;
    v1.x = sel ? hi32(f1[0][half]) : lo32(f1[0][half]);
    v1.y = sel ? hi32(f1[1][half]) : lo32(f1[1][half]);
    v1.z = sel ? hi32(f1[2][half]) : lo32(f1[2][half]);
    v1.w = sel ? hi32(f1[3][half]) : lo32(f1[3][half]);
    v2.x = sel ? hi32(f2[0][half]) : lo32(f2[0][half]);
    v2.y = sel ? hi32(f2[1][half]) : lo32(f2[1][half]);
    v2.z = sel ? hi32(f2[2][half]) : lo32(f2[2][half]);
    v2.w = sel ? hi32(f2[3][half]) : lo32(f2[3][half]);
    int d = dt0 + d0 + du;
    *reinterpret_cast<float4*>(&g_fv1[(b*DIM + d)*KCL + k0]) = v1;
    *reinterpret_cast<float4*>(&g_fv2[(b*DIM + d)*KCL + k0]) = v2;
  }
}

// ---------------- K5a: FV transforms + per-(b,k) and per-b sumsq ------------
__global__ __launch_bounds__(256) void fv_transform_kernel(
    const float* __restrict__ covw, const float* __restrict__ cw2w){
  int b = blockIdx.y, chunk = blockIdx.x;
  int tid = threadIdx.x;
  int k = tid & 63, dg = tid >> 6;
  float asum_k = g_asum[b*KCL + k];
  float pcol = 0.f, pn2 = 0.f;
  #pragma unroll 4
  for (int i=0;i<32;i++){
    int d = chunk*128 + i*4 + dg;
    int widx = d*KCL + k;
    int idx  = (b*DIM + d)*KCL + k;
    float cw2 = cw2w[widx];
    float cov = covw[widx];
    float cwv = cov*cov + 1e-6f;
    float f1r = g_fv1[idx], f2r = g_fv2[idx];
    float f1t = (f1r - asum_k*cw2) / cwv;
    float f2t = (asum_k*cw2*cw2 + f2r - 2.f*f1r*cw2) / (cwv*cwv) - asum_k;
    g_fv1[idx] = f1t; g_fv2[idx] = f2t;
    pcol += f1t*f1t; pn2 += f2t*f2t;
  }
  __shared__ float sCol[KCL];
  __shared__ float sw[8];
  if (tid < KCL) sCol[tid] = 0.f;
  __syncthreads();
  atomicAdd(&sCol[k], pcol);
  #pragma unroll
  for (int o=16;o>0;o>>=1) pn2 += __shfl_xor_sync(0xffffffffu, pn2, o);
  if ((tid&31)==0) sw[tid>>5] = pn2;
  __syncthreads();
  if (tid < KCL) atomicAdd(&g_colnorm[b*KCL + tid], sCol[tid]);
  if (tid == 0){
    float t=0.f;
    #pragma unroll
    for (int i=0;i<8;i++) t += sw[i];
    atomicAdd(&g_norm2[b], t);
  }
}

// ---------------- K5b: fv1 column-normalize, fv2 full-normalize, stage fvcat
__global__ __launch_bounds__(256) void fv_norm_kernel(){
  int b = blockIdx.y, chunk = blockIdx.x;
  int tid = threadIdx.x;
  int k = tid & 63, dg = tid >> 6;
  float inv1 = 1.f / fmaxf(sqrtf(g_colnorm[b*KCL + k]), 1e-12f);
  float inv2 = 1.f / fmaxf(sqrtf(g_norm2[b]), 1e-12f);
  float p1 = 0.f;
  #pragma unroll 4
  for (int i=0;i<32;i++){
    int d = chunk*128 + i*4 + dg;
    int idx = (b*DIM + d)*KCL + k;
    float f1 = g_fv1[idx] * inv1;
    g_fvcat[b*IN2 + d*KCL + k] = f1;
    p1 += f1*f1;
    g_fvcat[b*IN2 + DIM*KCL + d*KCL + k] = g_fv2[idx] * inv2;
  }
  #pragma unroll
  for (int o=16;o>0;o>>=1) p1 += __shfl_xor_sync(0xffffffffu, p1, o);
  __shared__ float sw[8];
  if ((tid&31)==0) sw[tid>>5] = p1;
  __syncthreads();
  if (tid == 0){
    float t=0.f;
    #pragma unroll
    for (int i=0;i<8;i++) t += sw[i];
    atomicAdd(&g_norm1[b], t);
  }
}

// ---------------- K6/K7a: out[32,1024] += A[32,chunk] @ W[chunk,1024] -------
// which=0: A=g_fvcat -> g_fvout (hidden1), fv1-half scaled by 1/||fv1||.
// which=1: A=g_fvout -> g_gates.
// block 128 threads, o-tile 128; thread tile 4b x 8o = 16 ffma2 / k-step.
#define FC_KT 16
__global__ __launch_bounds__(128) void gemm_fc_kernel(
    const float* __restrict__ W, int lda, int ichunk, int which){
  const float* A = which ? g_fvout : g_fvcat;
  float* out     = which ? g_gates : g_fvout;
  __shared__ float Ws[FC_KT][128];
  __shared__ float fs[FC_KT][32];
  int tid = threadIdx.x;
  int o0 = blockIdx.x * 128;
  int i0 = blockIdx.y * ichunk;
  int og = tid & 15, bg = tid >> 4;        // 16 x 8
  int o_local = og*8, b_local = bg*4;
  // per-batch scale for fv1 half (final full-vector l2 norm folded in)
  int lc = tid & 31;
  float sc = 1.f;
  if (which == 0 && i0 < DIM*KCL)
    sc = 1.f / fmaxf(sqrtf(g_norm1[lc]), 1e-12f);

  ull acc[4][4];
  #pragma unroll
  for (int bb=0;bb<4;bb++)
    #pragma unroll
    for (int j=0;j<4;j++) acc[bb][j] = 0ull;

  int rq = tid >> 5;                        // 0..3
  for (int ic=0; ic<ichunk; ic+=FC_KT){
    int i = i0 + ic;
    #pragma unroll
    for (int p=0;p<4;p++){
      int r = p*4 + (tid>>5);
      int c = (tid&31)*4;
      *reinterpret_cast<float4*>(&Ws[r][c]) =
          *reinterpret_cast<const float4*>(&W[(i+r)*OUTF + o0 + c]);
    }
    {
      float4 va = *reinterpret_cast<const float4*>(&A[lc*lda + i + rq*4]);
      fs[rq*4+0][lc] = va.x * sc;
      fs[rq*4+1][lc] = va.y * sc;
      fs[rq*4+2][lc] = va.z * sc;
      fs[rq*4+3][lc] = va.w * sc;
    }
    __syncthreads();
    #pragma unroll
    for (int ii=0; ii<FC_KT; ii++){
      const ull* wp = reinterpret_cast<const ull*>(&Ws[ii][o_local]);
      ull w0=wp[0], w1=wp[1], w2=wp[2], w3=wp[3];
      float4 av = *reinterpret_cast<const float4*>(&fs[ii][b_local]);
      ull a0 = pack2(av.x,av.x), a1 = pack2(av.y,av.y);
      ull a2 = pack2(av.z,av.z), a3 = pack2(av.w,av.w);
      ffma2(acc[0][0], a0, w0); ffma2(acc[0][1], a0, w1);
      ffma2(acc[0][2], a0, w2); ffma2(acc[0][3], a0, w3);
      ffma2(acc[1][0], a1, w0); ffma2(acc[1][1], a1, w1);
      ffma2(acc[1][2], a1, w2); ffma2(acc[1][3], a1, w3);
      ffma2(acc[2][0], a2, w0); ffma2(acc[2][1], a2, w1);
      ffma2(acc[2][2], a2, w2); ffma2(acc[2][3], a2, w3);
      ffma2(acc[3][0], a3, w0); ffma2(acc[3][1], a3, w1);
      ffma2(acc[3][2], a3, w2); ffma2(acc[3][3], a3, w3);
    }
    __syncthreads();
  }
  #pragma unroll
  for (int bb=0;bb<4;bb++)
    #pragma unroll
    for (int j=0;j<4;j++){
      int base = (b_local+bb)*OUTF + o0 + o_local + j*2;
      atomicAdd(&out[base],   lo32(acc[bb][j]));
      atomicAdd(&out[base+1], hi32(acc[bb][j]));
    }
}

// ---------------- K7b: BN2 (batch stats over 32) + sigmoid gate -------------
__global__ __launch_bounds__(256) void bn2_gate_kernel(
    const float* __restrict__ g2, const float* __restrict__ b2,
    float* __restrict__ out){
  int o = blockIdx.x*blockDim.x + threadIdx.x;   // 0..1023
  float m=0.f, s=0.f;
  #pragma unroll 8
  for (int b=0;b<BATCH;b++){ float v = g_gates[b*OUTF + o]; m += v; s += v*v; }
  m *= (1.f/BATCH);
  float var = s*(1.f/BATCH) - m*m;
  float rs = rsqrtf(var + 1e-5f);
  float ga = g2[o], be = b2[o];
  #pragma unroll 8
  for (int b=0;b<BATCH;b++){
    float v = (g_gates[b*OUTF + o] - m)*rs*ga + be;
    float sig = 1.f/(1.f + expf(-v));
    out[b*OUTF + o] = g_fvout[b*OUTF + o] * sig;
  }
}

// ---------------------------------------------------------------------------
extern "C" void kernel_launch(void* const* d_in, const int* in_sizes, int n_in,
                              void* d_out, int out_size){
  const float* x   = (const float*)d_in[0];   // [32,512,1024]
  const float* wc  = (const float*)d_in[1];   // [1024,64]
  const float* cov = (const float*)d_in[2];   // [1024,64]
  const float* cw2 = (const float*)d_in[3];   // [1,1024,64]
  const float* w1  = (const float*)d_in[4];   // [131072,1024]
  const float* g1  = (const float*)d_in[5];   // [64]
  const float* b1  = (const float*)d_in[6];   // [64]
  const float* wg  = (const float*)d_in[7];   // [1024,1024]
  const float* g2  = (const float*)d_in[8];   // [1024]
  const float* b2  = (const float*)d_in[9];   // [1024]
  float* out = (float*)d_out;                 // [32,1024]

  zero_kernel<<<128, 256>>>();
  gemm_act_kernel<<<256, 256>>>(x, wc);
  bn_softmax_kernel<<<2048, 256>>>(g1, b1);
  einsum_kernel<<<dim3(16, 32), 256>>>(x);
  fv_transform_kernel<<<dim3(8, 32), 256>>>(cov, cw2);
  fv_norm_kernel<<<dim3(8, 32), 256>>>();
  gemm_fc_kernel<<<dim3(8, 64), 128>>>(w1, IN2, 2048, 0);  // hidden1
  gemm_fc_kernel<<<dim3(8, 8),  128>>>(wg, OUTF, 128, 1);  // gating
  bn2_gate_kernel<<<4, 256>>>(g2, b2, out);
}